// round 2
// baseline (speedup 1.0000x reference)
#include <cuda_runtime.h>
#include <math.h>
#include <float.h>

// ----------------------------------------------------------------------------
// HierarchicalLoss: total = 0.5*MLM_CE + 0.2*InfoNCE(line) + 0.2*InfoNCE(quat)
//                         + 0.1*Sonnet_selfNCE
// Key optimization: only ~15% of MLM rows have a real label; ignored rows are
// skipped entirely (no logits traffic). Traffic floor ~75MB instead of 500MB.
// ----------------------------------------------------------------------------

#define INV_TEMP (1.0f / 0.07f)

__device__ float g_partial[4];     // [mlm_sum, line_sum, quat_sum, sonnet_sum]
__device__ int   g_mlm_count;
__device__ int   g_label_stride;   // 1 = int32 labels, 2 = int64 labels (read low word)
__device__ float g_invnorm[1024];  // inverse L2 norms for all small-matrix rows

// ---- streaming logsumexp helpers -------------------------------------------
__device__ __forceinline__ void lse_upd(float& m, float& s, float x) {
    if (x > m) { s = s * __expf(m - x) + 1.0f; m = x; }
    else       { s += __expf(x - m); }
}
__device__ __forceinline__ void lse_combine(float& m, float& s, float m2, float s2) {
    if (s2 <= 0.0f) return;
    if (m2 > m) { s = s * __expf(m - m2) + s2; m = m2; }
    else        { s += s2 * __expf(m2 - m); }
}

// ---- kernel 0: zero accumulators + detect label dtype ----------------------
// int64 little-endian: every odd 32-bit word is the hi word, always 0 or -1
// (labels are -100 or in [0, 30522)). int32 case: odd words are mostly -100
// (85% of labels are ignore), so the check trips immediately.
__global__ void init_detect_kernel(const int* __restrict__ lbl32, int nrows) {
    __shared__ int bad;
    int tid = threadIdx.x;
    if (tid == 0) bad = 0;
    __syncthreads();
    for (int i = tid; i < nrows / 2; i += blockDim.x) {
        int hi = lbl32[2 * i + 1];
        if (hi != 0 && hi != -1) bad = 1;   // benign race: any write sets it
    }
    __syncthreads();
    if (tid == 0) {
        g_label_stride = bad ? 1 : 2;
        g_partial[0] = 0.0f; g_partial[1] = 0.0f;
        g_partial[2] = 0.0f; g_partial[3] = 0.0f;
        g_mlm_count = 0;
    }
}

// ---- kernel 1: MLM cross-entropy (one block per row, early exit) -----------
__global__ __launch_bounds__(512) void mlm_kernel(
    const float* __restrict__ logits, const int* __restrict__ lbl32, int V)
{
    int row = blockIdx.x;
    int stride = g_label_stride;
    int lbl = lbl32[(size_t)row * stride];   // low word is correct for int64 too
    if (lbl < 0) return;                     // ignore_index = -100 -> zero traffic

    const float* __restrict__ x = logits + (size_t)row * V;
    const int T = 512;
    int tid = threadIdx.x;

    float m0 = -FLT_MAX, m1 = -FLT_MAX, m2 = -FLT_MAX, m3 = -FLT_MAX;
    float s0 = 0.f, s1 = 0.f, s2 = 0.f, s3 = 0.f;

    int i = tid;
    for (; i + 3 * T < V; i += 4 * T) {
        float x0 = __ldcs(x + i);
        float x1 = __ldcs(x + i + T);
        float x2 = __ldcs(x + i + 2 * T);
        float x3 = __ldcs(x + i + 3 * T);
        lse_upd(m0, s0, x0);
        lse_upd(m1, s1, x1);
        lse_upd(m2, s2, x2);
        lse_upd(m3, s3, x3);
    }
    for (; i < V; i += T) lse_upd(m0, s0, __ldcs(x + i));

    lse_combine(m0, s0, m1, s1);
    lse_combine(m2, s2, m3, s3);
    lse_combine(m0, s0, m2, s2);

    for (int o = 16; o; o >>= 1) {
        float mm = __shfl_xor_sync(0xffffffffu, m0, o);
        float ss = __shfl_xor_sync(0xffffffffu, s0, o);
        lse_combine(m0, s0, mm, ss);
    }
    __shared__ float shm[16], shs[16];
    int w = tid >> 5;
    if ((tid & 31) == 0) { shm[w] = m0; shs[w] = s0; }
    __syncthreads();
    if (tid == 0) {
        float M = shm[0], S = shs[0];
        #pragma unroll
        for (int k = 1; k < 16; k++) lse_combine(M, S, shm[k], shs[k]);
        float xl = __ldg(x + lbl);
        float nll = M + logf(S) - xl;
        atomicAdd(&g_partial[0], nll);
        atomicAdd(&g_mlm_count, 1);
    }
}

// ---- kernel 2: inverse L2 norms for all small-matrix rows ------------------
__global__ __launch_bounds__(256) void norms_kernel(
    const float* p0, const float* p1, const float* p2, const float* p3,
    const float* p4, const float* p5, const float* p6,
    int c0, int c1, int c2, int c3, int c4, int c5, int c6, int D)
{
    const float* ptrs[7] = {p0, p1, p2, p3, p4, p5, p6};
    int cnt[7] = {c0, c1, c2, c3, c4, c5, c6};
    int idx = blockIdx.x, off = 0, seg = 0;
    while (idx >= cnt[seg]) { idx -= cnt[seg]; off += cnt[seg]; seg++; }
    const float* row = ptrs[seg] + (size_t)idx * D;

    float p = 0.f;
    for (int k = threadIdx.x; k < D; k += 256) { float v = row[k]; p += v * v; }
    for (int o = 16; o; o >>= 1) p += __shfl_xor_sync(0xffffffffu, p, o);
    __shared__ float red[8];
    if ((threadIdx.x & 31) == 0) red[threadIdx.x >> 5] = p;
    __syncthreads();
    if (threadIdx.x == 0) {
        float s = 0.f;
        #pragma unroll
        for (int k = 0; k < 8; k++) s += red[k];
        g_invnorm[off + idx] = 1.0f / fmaxf(sqrtf(s), 1e-12f);
    }
}

// ---- kernel 3: fused InfoNCE(line) + InfoNCE(quat) + sonnet loss -----------
__global__ __launch_bounds__(256) void small_losses_kernel(
    const float* __restrict__ LA, const float* __restrict__ LP, const float* __restrict__ LN,
    const float* __restrict__ QA, const float* __restrict__ QP, const float* __restrict__ QN,
    const float* __restrict__ SE,
    int PL, int NL, int PQ, int NQ, int BS, int D,
    int oLA, int oLP, int oLN, int oQA, int oQP, int oQN, int oSE)
{
    __shared__ float a_s[1024];
    __shared__ float red[16];
    __shared__ float sh_pos;

    int b = blockIdx.x;
    int tid = threadIdx.x;

    if (b >= PL + PQ) {
        // ---- sonnet block (B x B self-similarity NCE) ----
        __shared__ float sim[256];
        __shared__ float invn_s[32];
        if (tid < BS) invn_s[tid] = g_invnorm[oSE + tid];
        __syncthreads();
        if (tid < BS * BS) {
            int ii = tid / BS, jj = tid % BS;
            const float* ei = SE + (size_t)ii * D;
            const float* ej = SE + (size_t)jj * D;
            float d = 0.f;
            for (int k = 0; k < D; k++) d += ei[k] * ej[k];
            sim[tid] = d * invn_s[ii] * invn_s[jj] * INV_TEMP;
        }
        __syncthreads();
        if (tid < BS) {
            float M = -FLT_MAX, S = 0.f;
            for (int j = 0; j < BS; j++) lse_upd(M, S, sim[tid * BS + j]);
            float loss = M + logf(S) - sim[tid * BS + tid];
            atomicAdd(&g_partial[3], loss);
        }
        return;
    }

    // ---- InfoNCE block (one anchor per block) ----
    const float* A; const float* P; const float* Nn;
    const float* inva; const float* invp; const float* invn;
    float* accum; int i, Ncnt;
    if (b < PL) {
        A = LA; P = LP; Nn = LN; i = b; Ncnt = NL;
        inva = g_invnorm + oLA; invp = g_invnorm + oLP; invn = g_invnorm + oLN;
        accum = &g_partial[1];
    } else {
        A = QA; P = QP; Nn = QN; i = b - PL; Ncnt = NQ;
        inva = g_invnorm + oQA; invp = g_invnorm + oQP; invn = g_invnorm + oQN;
        accum = &g_partial[2];
    }

    // stage normalized anchor in shared
    float ia = inva[i];
    for (int k = tid; k < D; k += 256) a_s[k] = A[(size_t)i * D + k] * ia;
    __syncthreads();

    // positive similarity: full-block dot product
    float part = 0.f;
    for (int k = tid; k < D; k += 256) part += a_s[k] * P[(size_t)i * D + k];
    for (int o = 16; o; o >>= 1) part += __shfl_xor_sync(0xffffffffu, part, o);
    if ((tid & 31) == 0) red[tid >> 5] = part;
    __syncthreads();
    if (tid == 0) {
        float s = 0.f;
        #pragma unroll
        for (int w = 0; w < 8; w++) s += red[w];
        sh_pos = s * invp[i] * INV_TEMP;
    }
    __syncthreads();
    float pos = sh_pos;

    // negatives: warp-per-negative, coalesced, streaming logsumexp per warp
    int w = tid >> 5, lane = tid & 31;
    float m = -FLT_MAX, s = 0.f;
    for (int j = w; j < Ncnt; j += 8) {
        const float* nr = Nn + (size_t)j * D;
        float d = 0.f;
        for (int k = lane; k < D; k += 32) d += a_s[k] * nr[k];
        for (int o = 16; o; o >>= 1) d += __shfl_xor_sync(0xffffffffu, d, o);
        float simv = d * invn[j] * INV_TEMP;
        lse_upd(m, s, simv);
    }
    __syncthreads();           // red[] reuse barrier
    if (lane == 0) { red[w * 2] = m; red[w * 2 + 1] = s; }
    __syncthreads();
    if (tid == 0) {
        float M = pos, S = 1.0f;  // positive term included in logits row
        #pragma unroll
        for (int ww = 0; ww < 8; ww++) lse_combine(M, S, red[2 * ww], red[2 * ww + 1]);
        atomicAdd(accum, M + logf(S) - pos);
    }
}

// ---- kernel 4: final weighted combination ----------------------------------
__global__ void finalize_kernel(float* __restrict__ out,
                                float invPL, float invPQ, float invBS)
{
    if (threadIdx.x == 0 && blockIdx.x == 0) {
        float mlm = g_partial[0] / fmaxf((float)g_mlm_count, 1.0f);
        out[0] = 0.5f * mlm
               + 0.2f * g_partial[1] * invPL
               + 0.2f * g_partial[2] * invPQ
               + 0.1f * g_partial[3] * invBS;
    }
}

// ----------------------------------------------------------------------------
extern "C" void kernel_launch(void* const* d_in, const int* in_sizes, int n_in,
                              void* d_out, int out_size)
{
    const float* mlm_logits = (const float*)d_in[0];
    const int*   labels     = (const int*)d_in[1];   // int32 or int64 (auto-detected)
    const float* LA = (const float*)d_in[2];
    const float* LP = (const float*)d_in[3];
    const float* LN = (const float*)d_in[4];
    const float* QA = (const float*)d_in[5];
    const float* QP = (const float*)d_in[6];
    const float* QN = (const float*)d_in[7];
    const float* SE = (const float*)d_in[8];

    const int D  = 768;
    int NR  = in_sizes[1];                 // B*S rows
    int V   = in_sizes[0] / NR;            // vocab
    int PL  = in_sizes[2] / D;
    int PLp = in_sizes[3] / D;
    int NL  = in_sizes[4] / D;
    int PQ  = in_sizes[5] / D;
    int PQp = in_sizes[6] / D;
    int NQ  = in_sizes[7] / D;
    int BS  = in_sizes[8] / D;

    int oLA = 0;
    int oLP = oLA + PL;
    int oLN = oLP + PLp;
    int oQA = oLN + NL;
    int oQP = oQA + PQ;
    int oQN = oQP + PQp;
    int oSE = oQN + NQ;
    int totalRows = oSE + BS;

    init_detect_kernel<<<1, 256>>>(labels, NR);
    mlm_kernel<<<NR, 512>>>(mlm_logits, labels, V);
    norms_kernel<<<totalRows, 256>>>(LA, LP, LN, QA, QP, QN, SE,
                                     PL, PLp, NL, PQ, PQp, NQ, BS, D);
    small_losses_kernel<<<PL + PQ + 1, 256>>>(LA, LP, LN, QA, QP, QN, SE,
                                              PL, NL, PQ, NQ, BS, D,
                                              oLA, oLP, oLN, oQA, oQP, oQN, oSE);
    finalize_kernel<<<1, 32>>>((float*)d_out,
                               1.0f / (float)PL, 1.0f / (float)PQ, 1.0f / (float)BS);
}

// round 3
// speedup vs baseline: 1.4001x; 1.4001x over previous
#include <cuda_runtime.h>
#include <math.h>
#include <float.h>
#include <stdint.h>

// ----------------------------------------------------------------------------
// HierarchicalLoss: total = 0.5*MLM_CE + 0.2*InfoNCE(line) + 0.2*InfoNCE(quat)
//                         + 0.1*Sonnet_selfNCE
// R3: vectorized float4 paths everywhere; 4-way negative ILP in InfoNCE;
//     8-chain streaming LSE in MLM with 128-bit loads.
// ----------------------------------------------------------------------------

#define INV_TEMP (1.0f / 0.07f)

__device__ float g_partial[4];     // [mlm_sum, line_sum, quat_sum, sonnet_sum]
__device__ int   g_mlm_count;
__device__ int   g_label_stride;   // 1 = int32 labels, 2 = int64 labels (read low word)
__device__ float g_invnorm[1024];  // inverse L2 norms for all small-matrix rows

// ---- streaming logsumexp helpers -------------------------------------------
__device__ __forceinline__ void lse_upd(float& m, float& s, float x) {
    if (x > m) { s = s * __expf(m - x) + 1.0f; m = x; }
    else       { s += __expf(x - m); }
}
__device__ __forceinline__ void lse_combine(float& m, float& s, float m2, float s2) {
    if (s2 <= 0.0f) return;
    if (m2 > m) { s = s * __expf(m - m2) + s2; m = m2; }
    else        { s += s2 * __expf(m2 - m); }
}

// ---- kernel 0: zero accumulators + detect label dtype ----------------------
// int64 LE: odd 32-bit words are hi words, always 0 or -1 (labels are -100 or
// [0,30522)). int32 case trips immediately (85% of labels are -100).
__global__ void init_detect_kernel(const int* __restrict__ lbl32, int nrows) {
    __shared__ int bad;
    int tid = threadIdx.x;
    if (tid == 0) bad = 0;
    __syncthreads();
    for (int i = tid; i < nrows / 2; i += blockDim.x) {
        int hi = lbl32[2 * i + 1];
        if (hi != 0 && hi != -1) bad = 1;
    }
    __syncthreads();
    if (tid == 0) {
        g_label_stride = bad ? 1 : 2;
        g_partial[0] = 0.0f; g_partial[1] = 0.0f;
        g_partial[2] = 0.0f; g_partial[3] = 0.0f;
        g_mlm_count = 0;
    }
}

// ---- kernel 1: MLM cross-entropy: block per row, early exit, float4 --------
__global__ __launch_bounds__(512) void mlm_kernel(
    const float* __restrict__ logits, const int* __restrict__ lbl32, int V)
{
    int row = blockIdx.x;
    int lbl = lbl32[(size_t)row * g_label_stride];
    if (lbl < 0) return;                     // ignore_index -> zero logits traffic

    const float* __restrict__ x = logits + (size_t)row * V;
    int tid = threadIdx.x;

    float m[8], s[8];
    #pragma unroll
    for (int c = 0; c < 8; c++) { m[c] = -FLT_MAX; s[c] = 0.0f; }

    // alignment prologue: row base is either 16B- or only 8B-aligned
    int head = (((uintptr_t)x) & 15) ? 2 : 0;
    if (tid < head) lse_upd(m[0], s[0], x[tid]);

    const float4* __restrict__ x4 = (const float4*)(x + head);
    int n4 = (V - head) >> 2;
    int tail = (V - head) & 3;

    int i = tid;
    for (; i + 512 < n4; i += 1024) {
        float4 v0 = __ldcs(x4 + i);
        float4 v1 = __ldcs(x4 + i + 512);
        lse_upd(m[0], s[0], v0.x); lse_upd(m[1], s[1], v0.y);
        lse_upd(m[2], s[2], v0.z); lse_upd(m[3], s[3], v0.w);
        lse_upd(m[4], s[4], v1.x); lse_upd(m[5], s[5], v1.y);
        lse_upd(m[6], s[6], v1.z); lse_upd(m[7], s[7], v1.w);
    }
    for (; i < n4; i += 512) {
        float4 v0 = __ldcs(x4 + i);
        lse_upd(m[0], s[0], v0.x); lse_upd(m[1], s[1], v0.y);
        lse_upd(m[2], s[2], v0.z); lse_upd(m[3], s[3], v0.w);
    }
    if (tid < tail) lse_upd(m[4], s[4], x[head + 4 * n4 + tid]);

    // tree-combine 8 chains
    #pragma unroll
    for (int st = 4; st; st >>= 1)
        #pragma unroll
        for (int c = 0; c < 8; c++)
            if (c < st) lse_combine(m[c], s[c], m[c + st], s[c + st]);

    float M0 = m[0], S0 = s[0];
    for (int o = 16; o; o >>= 1) {
        float mm = __shfl_xor_sync(0xffffffffu, M0, o);
        float ss = __shfl_xor_sync(0xffffffffu, S0, o);
        lse_combine(M0, S0, mm, ss);
    }
    __shared__ float shm[16], shs[16];
    int w = tid >> 5;
    if ((tid & 31) == 0) { shm[w] = M0; shs[w] = S0; }
    __syncthreads();
    if (tid == 0) {
        float M = shm[0], S = shs[0];
        #pragma unroll
        for (int k = 1; k < 16; k++) lse_combine(M, S, shm[k], shs[k]);
        float xl = __ldg(x + lbl);
        atomicAdd(&g_partial[0], M + logf(S) - xl);
        atomicAdd(&g_mlm_count, 1);
    }
}

// ---- kernel 2: inverse L2 norms for all small-matrix rows ------------------
__global__ __launch_bounds__(256) void norms_kernel(
    const float* p0, const float* p1, const float* p2, const float* p3,
    const float* p4, const float* p5, const float* p6,
    int c0, int c1, int c2, int c3, int c4, int c5, int c6, int D)
{
    const float* ptrs[7] = {p0, p1, p2, p3, p4, p5, p6};
    int cnt[7] = {c0, c1, c2, c3, c4, c5, c6};
    int idx = blockIdx.x, off = 0, seg = 0;
    while (idx >= cnt[seg]) { idx -= cnt[seg]; off += cnt[seg]; seg++; }
    const float4* row = (const float4*)(ptrs[seg] + (size_t)idx * D);
    int D4 = D >> 2;

    float p = 0.f;
    for (int k = threadIdx.x; k < D4; k += 256) {
        float4 v = row[k];
        p += v.x * v.x + v.y * v.y + v.z * v.z + v.w * v.w;
    }
    for (int o = 16; o; o >>= 1) p += __shfl_xor_sync(0xffffffffu, p, o);
    __shared__ float red[8];
    if ((threadIdx.x & 31) == 0) red[threadIdx.x >> 5] = p;
    __syncthreads();
    if (threadIdx.x == 0) {
        float sm = 0.f;
        #pragma unroll
        for (int k = 0; k < 8; k++) sm += red[k];
        g_invnorm[off + idx] = 1.0f / fmaxf(sqrtf(sm), 1e-12f);
    }
}

// ---- kernel 3: fused InfoNCE(line) + InfoNCE(quat) + sonnet loss -----------
__global__ __launch_bounds__(256) void small_losses_kernel(
    const float* __restrict__ LA, const float* __restrict__ LP, const float* __restrict__ LN,
    const float* __restrict__ QA, const float* __restrict__ QP, const float* __restrict__ QN,
    const float* __restrict__ SE,
    int PL, int NL, int PQ, int NQ, int BS, int D,
    int oLA, int oLP, int oLN, int oQA, int oQP, int oQN, int oSE)
{
    __shared__ float4 a_s4[192];     // D=768 -> 192 float4 (normalized anchor)
    __shared__ float red[16];
    __shared__ float sh_pos;

    int b = blockIdx.x;
    int tid = threadIdx.x;
    int D4 = D >> 2;

    if (b >= PL + PQ) {
        // ---- sonnet block (B x B self-similarity NCE), float4 dots ----
        __shared__ float sim[256];
        __shared__ float invn_s[32];
        if (tid < BS) invn_s[tid] = g_invnorm[oSE + tid];
        __syncthreads();
        if (tid < BS * BS) {
            int ii = tid / BS, jj = tid % BS;
            const float4* ei = (const float4*)(SE + (size_t)ii * D);
            const float4* ej = (const float4*)(SE + (size_t)jj * D);
            float d = 0.f;
            #pragma unroll 4
            for (int k = 0; k < D4; k++) {
                float4 a = ei[k], c = ej[k];
                d += a.x * c.x + a.y * c.y + a.z * c.z + a.w * c.w;
            }
            sim[tid] = d * invn_s[ii] * invn_s[jj] * INV_TEMP;
        }
        __syncthreads();
        if (tid < BS) {
            float M = -FLT_MAX, S = 0.f;
            for (int j = 0; j < BS; j++) lse_upd(M, S, sim[tid * BS + j]);
            atomicAdd(&g_partial[3], M + logf(S) - sim[tid * BS + tid]);
        }
        return;
    }

    // ---- InfoNCE block (one anchor per block) ----
    const float* A; const float* P; const float* Nn;
    const float* inva; const float* invp; const float* invn;
    float* accum; int i, Ncnt;
    if (b < PL) {
        A = LA; P = LP; Nn = LN; i = b; Ncnt = NL;
        inva = g_invnorm + oLA; invp = g_invnorm + oLP; invn = g_invnorm + oLN;
        accum = &g_partial[1];
    } else {
        A = QA; P = QP; Nn = QN; i = b - PL; Ncnt = NQ;
        inva = g_invnorm + oQA; invp = g_invnorm + oQP; invn = g_invnorm + oQN;
        accum = &g_partial[2];
    }

    // stage normalized anchor in shared (float4)
    float ia = inva[i];
    const float4* Arow = (const float4*)(A + (size_t)i * D);
    for (int k = tid; k < D4; k += 256) {
        float4 v = Arow[k];
        a_s4[k] = make_float4(v.x * ia, v.y * ia, v.z * ia, v.w * ia);
    }
    __syncthreads();

    // positive similarity: full-block float4 dot
    {
        const float4* Prow = (const float4*)(P + (size_t)i * D);
        float part = 0.f;
        for (int k = tid; k < D4; k += 256) {
            float4 a = a_s4[k], p = Prow[k];
            part += a.x * p.x + a.y * p.y + a.z * p.z + a.w * p.w;
        }
        for (int o = 16; o; o >>= 1) part += __shfl_xor_sync(0xffffffffu, part, o);
        if ((tid & 31) == 0) red[tid >> 5] = part;
        __syncthreads();
        if (tid == 0) {
            float ssum = 0.f;
            #pragma unroll
            for (int w = 0; w < 8; w++) ssum += red[w];
            sh_pos = ssum * invp[i] * INV_TEMP;
        }
        __syncthreads();
    }
    float pos = sh_pos;

    // negatives: warp takes a contiguous chunk, 4 negatives in flight
    // (24 LDG.128 + 6 LDS.128 per pass, 4 interleaved shuffle trees)
    int w = tid >> 5, lane = tid & 31;
    int chunk = (Ncnt + 7) >> 3;
    int jbeg = w * chunk;
    int jend = min(jbeg + chunk, Ncnt);

    float m = -FLT_MAX, s = 0.f;
    for (int j = jbeg; j < jend; j += 4) {
        int nv = jend - j;                    // uniform within warp
        float d0 = 0.f, d1 = 0.f, d2 = 0.f, d3 = 0.f;
        const float4* n0 = (const float4*)(Nn + (size_t)(j + 0) * D);
        const float4* n1 = (const float4*)(Nn + (size_t)(j + 1) * D);
        const float4* n2 = (const float4*)(Nn + (size_t)(j + 2) * D);
        const float4* n3 = (const float4*)(Nn + (size_t)(j + 3) * D);
        #pragma unroll
        for (int p = 0; p < 6; p++) {         // 192 float4 / 32 lanes
            int kk = lane + 32 * p;
            float4 a = a_s4[kk];
            {            float4 v = n0[kk]; d0 += a.x*v.x + a.y*v.y + a.z*v.z + a.w*v.w; }
            if (nv > 1) { float4 v = n1[kk]; d1 += a.x*v.x + a.y*v.y + a.z*v.z + a.w*v.w; }
            if (nv > 2) { float4 v = n2[kk]; d2 += a.x*v.x + a.y*v.y + a.z*v.z + a.w*v.w; }
            if (nv > 3) { float4 v = n3[kk]; d3 += a.x*v.x + a.y*v.y + a.z*v.z + a.w*v.w; }
        }
        #pragma unroll
        for (int o = 16; o; o >>= 1) {
            d0 += __shfl_xor_sync(0xffffffffu, d0, o);
            d1 += __shfl_xor_sync(0xffffffffu, d1, o);
            d2 += __shfl_xor_sync(0xffffffffu, d2, o);
            d3 += __shfl_xor_sync(0xffffffffu, d3, o);
        }
        lse_upd(m, s, d0 * invn[j] * INV_TEMP);
        if (nv > 1) lse_upd(m, s, d1 * invn[j + 1] * INV_TEMP);
        if (nv > 2) lse_upd(m, s, d2 * invn[j + 2] * INV_TEMP);
        if (nv > 3) lse_upd(m, s, d3 * invn[j + 3] * INV_TEMP);
    }
    __syncthreads();          // red[] reuse barrier
    if (lane == 0) { red[w * 2] = m; red[w * 2 + 1] = s; }
    __syncthreads();
    if (tid == 0) {
        float M = pos, S = 1.0f;  // positive term included in logits row
        #pragma unroll
        for (int ww = 0; ww < 8; ww++) lse_combine(M, S, red[2 * ww], red[2 * ww + 1]);
        atomicAdd(accum, M + logf(S) - pos);
    }
}

// ---- kernel 4: final weighted combination ----------------------------------
__global__ void finalize_kernel(float* __restrict__ out,
                                float invPL, float invPQ, float invBS)
{
    if (threadIdx.x == 0 && blockIdx.x == 0) {
        float mlm = g_partial[0] / fmaxf((float)g_mlm_count, 1.0f);
        out[0] = 0.5f * mlm
               + 0.2f * g_partial[1] * invPL
               + 0.2f * g_partial[2] * invPQ
               + 0.1f * g_partial[3] * invBS;
    }
}

// ----------------------------------------------------------------------------
extern "C" void kernel_launch(void* const* d_in, const int* in_sizes, int n_in,
                              void* d_out, int out_size)
{
    const float* mlm_logits = (const float*)d_in[0];
    const int*   labels     = (const int*)d_in[1];
    const float* LA = (const float*)d_in[2];
    const float* LP = (const float*)d_in[3];
    const float* LN = (const float*)d_in[4];
    const float* QA = (const float*)d_in[5];
    const float* QP = (const float*)d_in[6];
    const float* QN = (const float*)d_in[7];
    const float* SE = (const float*)d_in[8];

    const int D  = 768;
    int NR  = in_sizes[1];
    int V   = in_sizes[0] / NR;
    int PL  = in_sizes[2] / D;
    int PLp = in_sizes[3] / D;
    int NL  = in_sizes[4] / D;
    int PQ  = in_sizes[5] / D;
    int PQp = in_sizes[6] / D;
    int NQ  = in_sizes[7] / D;
    int BS  = in_sizes[8] / D;

    int oLA = 0;
    int oLP = oLA + PL;
    int oLN = oLP + PLp;
    int oQA = oLN + NL;
    int oQP = oQA + PQ;
    int oQN = oQP + PQp;
    int oSE = oQN + NQ;
    int totalRows = oSE + BS;

    init_detect_kernel<<<1, 256>>>(labels, NR);
    mlm_kernel<<<NR, 512>>>(mlm_logits, labels, V);
    norms_kernel<<<totalRows, 256>>>(LA, LP, LN, QA, QP, QN, SE,
                                     PL, PLp, NL, PQ, PQp, NQ, BS, D);
    small_losses_kernel<<<PL + PQ + 1, 256>>>(LA, LP, LN, QA, QP, QN, SE,
                                              PL, NL, PQ, NQ, BS, D,
                                              oLA, oLP, oLN, oQA, oQP, oQN, oSE);
    finalize_kernel<<<1, 32>>>((float*)d_out,
                               1.0f / (float)PL, 1.0f / (float)PQ, 1.0f / (float)BS);
}

// round 4
// speedup vs baseline: 1.7498x; 1.2498x over previous
#include <cuda_runtime.h>
#include <math.h>
#include <float.h>
#include <stdint.h>

// ----------------------------------------------------------------------------
// HierarchicalLoss: total = 0.5*MLM_CE + 0.2*InfoNCE(line) + 0.2*InfoNCE(quat)
//                         + 0.1*Sonnet_selfNCE
// R4: sonnet loss restructured from 1 block with 16-way replayed uncoalesced
//     loads (70us straggler) to BS blocks using the coalesced warp-per-row
//     pattern. Everything else unchanged from R3.
// ----------------------------------------------------------------------------

#define INV_TEMP (1.0f / 0.07f)

__device__ float g_partial[4];     // [mlm_sum, line_sum, quat_sum, sonnet_sum]
__device__ int   g_mlm_count;
__device__ int   g_label_stride;   // 1 = int32 labels, 2 = int64 labels (read low word)
__device__ float g_invnorm[1024];  // inverse L2 norms for all small-matrix rows

// ---- streaming logsumexp helpers -------------------------------------------
__device__ __forceinline__ void lse_upd(float& m, float& s, float x) {
    if (x > m) { s = s * __expf(m - x) + 1.0f; m = x; }
    else       { s += __expf(x - m); }
}
__device__ __forceinline__ void lse_combine(float& m, float& s, float m2, float s2) {
    if (s2 <= 0.0f) return;
    if (m2 > m) { s = s * __expf(m - m2) + s2; m = m2; }
    else        { s += s2 * __expf(m2 - m); }
}

// ---- kernel 0: zero accumulators + detect label dtype ----------------------
__global__ void init_detect_kernel(const int* __restrict__ lbl32, int nrows) {
    __shared__ int bad;
    int tid = threadIdx.x;
    if (tid == 0) bad = 0;
    __syncthreads();
    for (int i = tid; i < nrows / 2; i += blockDim.x) {
        int hi = lbl32[2 * i + 1];
        if (hi != 0 && hi != -1) bad = 1;
    }
    __syncthreads();
    if (tid == 0) {
        g_label_stride = bad ? 1 : 2;
        g_partial[0] = 0.0f; g_partial[1] = 0.0f;
        g_partial[2] = 0.0f; g_partial[3] = 0.0f;
        g_mlm_count = 0;
    }
}

// ---- kernel 1: MLM cross-entropy: block per row, early exit, float4 --------
__global__ __launch_bounds__(512) void mlm_kernel(
    const float* __restrict__ logits, const int* __restrict__ lbl32, int V)
{
    int row = blockIdx.x;
    int lbl = lbl32[(size_t)row * g_label_stride];
    if (lbl < 0) return;                     // ignore_index -> zero logits traffic

    const float* __restrict__ x = logits + (size_t)row * V;
    int tid = threadIdx.x;

    float m[8], s[8];
    #pragma unroll
    for (int c = 0; c < 8; c++) { m[c] = -FLT_MAX; s[c] = 0.0f; }

    // alignment prologue: row base is either 16B- or only 8B-aligned
    int head = (((uintptr_t)x) & 15) ? 2 : 0;
    if (tid < head) lse_upd(m[0], s[0], x[tid]);

    const float4* __restrict__ x4 = (const float4*)(x + head);
    int n4 = (V - head) >> 2;
    int tail = (V - head) & 3;

    int i = tid;
    for (; i + 512 < n4; i += 1024) {
        float4 v0 = __ldcs(x4 + i);
        float4 v1 = __ldcs(x4 + i + 512);
        lse_upd(m[0], s[0], v0.x); lse_upd(m[1], s[1], v0.y);
        lse_upd(m[2], s[2], v0.z); lse_upd(m[3], s[3], v0.w);
        lse_upd(m[4], s[4], v1.x); lse_upd(m[5], s[5], v1.y);
        lse_upd(m[6], s[6], v1.z); lse_upd(m[7], s[7], v1.w);
    }
    for (; i < n4; i += 512) {
        float4 v0 = __ldcs(x4 + i);
        lse_upd(m[0], s[0], v0.x); lse_upd(m[1], s[1], v0.y);
        lse_upd(m[2], s[2], v0.z); lse_upd(m[3], s[3], v0.w);
    }
    if (tid < tail) lse_upd(m[4], s[4], x[head + 4 * n4 + tid]);

    #pragma unroll
    for (int st = 4; st; st >>= 1)
        #pragma unroll
        for (int c = 0; c < 8; c++)
            if (c < st) lse_combine(m[c], s[c], m[c + st], s[c + st]);

    float M0 = m[0], S0 = s[0];
    for (int o = 16; o; o >>= 1) {
        float mm = __shfl_xor_sync(0xffffffffu, M0, o);
        float ss = __shfl_xor_sync(0xffffffffu, S0, o);
        lse_combine(M0, S0, mm, ss);
    }
    __shared__ float shm[16], shs[16];
    int w = tid >> 5;
    if ((tid & 31) == 0) { shm[w] = M0; shs[w] = S0; }
    __syncthreads();
    if (tid == 0) {
        float M = shm[0], S = shs[0];
        #pragma unroll
        for (int k = 1; k < 16; k++) lse_combine(M, S, shm[k], shs[k]);
        float xl = __ldg(x + lbl);
        atomicAdd(&g_partial[0], M + logf(S) - xl);
        atomicAdd(&g_mlm_count, 1);
    }
}

// ---- kernel 2: inverse L2 norms for all small-matrix rows ------------------
__global__ __launch_bounds__(256) void norms_kernel(
    const float* p0, const float* p1, const float* p2, const float* p3,
    const float* p4, const float* p5, const float* p6,
    int c0, int c1, int c2, int c3, int c4, int c5, int c6, int D)
{
    const float* ptrs[7] = {p0, p1, p2, p3, p4, p5, p6};
    int cnt[7] = {c0, c1, c2, c3, c4, c5, c6};
    int idx = blockIdx.x, off = 0, seg = 0;
    while (idx >= cnt[seg]) { idx -= cnt[seg]; off += cnt[seg]; seg++; }
    const float4* row = (const float4*)(ptrs[seg] + (size_t)idx * D);
    int D4 = D >> 2;

    float p = 0.f;
    for (int k = threadIdx.x; k < D4; k += 256) {
        float4 v = row[k];
        p += v.x * v.x + v.y * v.y + v.z * v.z + v.w * v.w;
    }
    for (int o = 16; o; o >>= 1) p += __shfl_xor_sync(0xffffffffu, p, o);
    __shared__ float red[8];
    if ((threadIdx.x & 31) == 0) red[threadIdx.x >> 5] = p;
    __syncthreads();
    if (threadIdx.x == 0) {
        float sm = 0.f;
        #pragma unroll
        for (int k = 0; k < 8; k++) sm += red[k];
        g_invnorm[off + idx] = 1.0f / fmaxf(sqrtf(sm), 1e-12f);
    }
}

// ---- kernel 3: fused InfoNCE(line) + InfoNCE(quat) + sonnet loss -----------
__global__ __launch_bounds__(256) void small_losses_kernel(
    const float* __restrict__ LA, const float* __restrict__ LP, const float* __restrict__ LN,
    const float* __restrict__ QA, const float* __restrict__ QP, const float* __restrict__ QN,
    const float* __restrict__ SE,
    int PL, int NL, int PQ, int NQ, int BS, int D,
    int oLA, int oLP, int oLN, int oQA, int oQP, int oQN, int oSE)
{
    __shared__ float4 a_s4[192];     // D=768 -> 192 float4 (normalized anchor)
    __shared__ float red[16];
    __shared__ float sh_pos;

    int b = blockIdx.x;
    int tid = threadIdx.x;
    int D4 = D >> 2;

    if (b >= PL + PQ) {
        // ---- sonnet: one block per row ii, coalesced warp-per-jj dots ----
        int ii = b - (PL + PQ);
        float ia = g_invnorm[oSE + ii];
        const float4* Arow = (const float4*)(SE + (size_t)ii * D);
        for (int k = tid; k < D4; k += 256) {
            float4 v = Arow[k];
            a_s4[k] = make_float4(v.x * ia, v.y * ia, v.z * ia, v.w * ia);
        }
        __syncthreads();
        __shared__ float sh_sim[32];
        int w = tid >> 5, lane = tid & 31;
        for (int jj = w; jj < BS; jj += 8) {
            const float4* nr = (const float4*)(SE + (size_t)jj * D);
            float d = 0.f;
            #pragma unroll
            for (int p = 0; p < 6; p++) {      // 192 float4 / 32 lanes
                int kk = lane + 32 * p;
                float4 a = a_s4[kk], v = nr[kk];
                d += a.x * v.x + a.y * v.y + a.z * v.z + a.w * v.w;
            }
            #pragma unroll
            for (int o = 16; o; o >>= 1) d += __shfl_xor_sync(0xffffffffu, d, o);
            if (lane == 0) sh_sim[jj] = d * g_invnorm[oSE + jj] * INV_TEMP;
        }
        __syncthreads();
        if (tid == 0) {
            float M = -FLT_MAX, S = 0.f;
            for (int j = 0; j < BS; j++) lse_upd(M, S, sh_sim[j]);
            atomicAdd(&g_partial[3], M + logf(S) - sh_sim[ii]);
        }
        return;
    }

    // ---- InfoNCE block (one anchor per block) ----
    const float* A; const float* P; const float* Nn;
    const float* inva; const float* invp; const float* invn;
    float* accum; int i, Ncnt;
    if (b < PL) {
        A = LA; P = LP; Nn = LN; i = b; Ncnt = NL;
        inva = g_invnorm + oLA; invp = g_invnorm + oLP; invn = g_invnorm + oLN;
        accum = &g_partial[1];
    } else {
        A = QA; P = QP; Nn = QN; i = b - PL; Ncnt = NQ;
        inva = g_invnorm + oQA; invp = g_invnorm + oQP; invn = g_invnorm + oQN;
        accum = &g_partial[2];
    }

    // stage normalized anchor in shared (float4)
    float ia = inva[i];
    const float4* Arow = (const float4*)(A + (size_t)i * D);
    for (int k = tid; k < D4; k += 256) {
        float4 v = Arow[k];
        a_s4[k] = make_float4(v.x * ia, v.y * ia, v.z * ia, v.w * ia);
    }
    __syncthreads();

    // positive similarity: full-block float4 dot
    {
        const float4* Prow = (const float4*)(P + (size_t)i * D);
        float part = 0.f;
        for (int k = tid; k < D4; k += 256) {
            float4 a = a_s4[k], p = Prow[k];
            part += a.x * p.x + a.y * p.y + a.z * p.z + a.w * p.w;
        }
        for (int o = 16; o; o >>= 1) part += __shfl_xor_sync(0xffffffffu, part, o);
        if ((tid & 31) == 0) red[tid >> 5] = part;
        __syncthreads();
        if (tid == 0) {
            float ssum = 0.f;
            #pragma unroll
            for (int w = 0; w < 8; w++) ssum += red[w];
            sh_pos = ssum * invp[i] * INV_TEMP;
        }
        __syncthreads();
    }
    float pos = sh_pos;

    // negatives: warp takes a contiguous chunk, 4 negatives in flight
    int w = tid >> 5, lane = tid & 31;
    int chunk = (Ncnt + 7) >> 3;
    int jbeg = w * chunk;
    int jend = min(jbeg + chunk, Ncnt);

    float m = -FLT_MAX, s = 0.f;
    for (int j = jbeg; j < jend; j += 4) {
        int nv = jend - j;                    // uniform within warp
        float d0 = 0.f, d1 = 0.f, d2 = 0.f, d3 = 0.f;
        const float4* n0 = (const float4*)(Nn + (size_t)(j + 0) * D);
        const float4* n1 = (const float4*)(Nn + (size_t)(j + 1) * D);
        const float4* n2 = (const float4*)(Nn + (size_t)(j + 2) * D);
        const float4* n3 = (const float4*)(Nn + (size_t)(j + 3) * D);
        #pragma unroll
        for (int p = 0; p < 6; p++) {
            int kk = lane + 32 * p;
            float4 a = a_s4[kk];
            {            float4 v = n0[kk]; d0 += a.x*v.x + a.y*v.y + a.z*v.z + a.w*v.w; }
            if (nv > 1) { float4 v = n1[kk]; d1 += a.x*v.x + a.y*v.y + a.z*v.z + a.w*v.w; }
            if (nv > 2) { float4 v = n2[kk]; d2 += a.x*v.x + a.y*v.y + a.z*v.z + a.w*v.w; }
            if (nv > 3) { float4 v = n3[kk]; d3 += a.x*v.x + a.y*v.y + a.z*v.z + a.w*v.w; }
        }
        #pragma unroll
        for (int o = 16; o; o >>= 1) {
            d0 += __shfl_xor_sync(0xffffffffu, d0, o);
            d1 += __shfl_xor_sync(0xffffffffu, d1, o);
            d2 += __shfl_xor_sync(0xffffffffu, d2, o);
            d3 += __shfl_xor_sync(0xffffffffu, d3, o);
        }
        lse_upd(m, s, d0 * invn[j] * INV_TEMP);
        if (nv > 1) lse_upd(m, s, d1 * invn[j + 1] * INV_TEMP);
        if (nv > 2) lse_upd(m, s, d2 * invn[j + 2] * INV_TEMP);
        if (nv > 3) lse_upd(m, s, d3 * invn[j + 3] * INV_TEMP);
    }
    __syncthreads();          // red[] reuse barrier
    if (lane == 0) { red[w * 2] = m; red[w * 2 + 1] = s; }
    __syncthreads();
    if (tid == 0) {
        float M = pos, S = 1.0f;  // positive term included in logits row
        #pragma unroll
        for (int ww = 0; ww < 8; ww++) lse_combine(M, S, red[2 * ww], red[2 * ww + 1]);
        atomicAdd(accum, M + logf(S) - pos);
    }
}

// ---- kernel 4: final weighted combination ----------------------------------
__global__ void finalize_kernel(float* __restrict__ out,
                                float invPL, float invPQ, float invBS)
{
    if (threadIdx.x == 0 && blockIdx.x == 0) {
        float mlm = g_partial[0] / fmaxf((float)g_mlm_count, 1.0f);
        out[0] = 0.5f * mlm
               + 0.2f * g_partial[1] * invPL
               + 0.2f * g_partial[2] * invPQ
               + 0.1f * g_partial[3] * invBS;
    }
}

// ----------------------------------------------------------------------------
extern "C" void kernel_launch(void* const* d_in, const int* in_sizes, int n_in,
                              void* d_out, int out_size)
{
    const float* mlm_logits = (const float*)d_in[0];
    const int*   labels     = (const int*)d_in[1];
    const float* LA = (const float*)d_in[2];
    const float* LP = (const float*)d_in[3];
    const float* LN = (const float*)d_in[4];
    const float* QA = (const float*)d_in[5];
    const float* QP = (const float*)d_in[6];
    const float* QN = (const float*)d_in[7];
    const float* SE = (const float*)d_in[8];

    const int D  = 768;
    int NR  = in_sizes[1];
    int V   = in_sizes[0] / NR;
    int PL  = in_sizes[2] / D;
    int PLp = in_sizes[3] / D;
    int NL  = in_sizes[4] / D;
    int PQ  = in_sizes[5] / D;
    int PQp = in_sizes[6] / D;
    int NQ  = in_sizes[7] / D;
    int BS  = in_sizes[8] / D;

    int oLA = 0;
    int oLP = oLA + PL;
    int oLN = oLP + PLp;
    int oQA = oLN + NL;
    int oQP = oQA + PQ;
    int oQN = oQP + PQp;
    int oSE = oQN + NQ;
    int totalRows = oSE + BS;

    init_detect_kernel<<<1, 256>>>(labels, NR);
    mlm_kernel<<<NR, 512>>>(mlm_logits, labels, V);
    norms_kernel<<<totalRows, 256>>>(LA, LP, LN, QA, QP, QN, SE,
                                     PL, PLp, NL, PQ, PQp, NQ, BS, D);
    small_losses_kernel<<<PL + PQ + BS, 256>>>(LA, LP, LN, QA, QP, QN, SE,
                                               PL, NL, PQ, NQ, BS, D,
                                               oLA, oLP, oLN, oQA, oQP, oQN, oSE);
    finalize_kernel<<<1, 32>>>((float*)d_out,
                               1.0f / (float)PL, 1.0f / (float)PQ, 1.0f / (float)BS);
}

// round 8
// speedup vs baseline: 2.4043x; 1.3740x over previous
#include <cuda_runtime.h>
#include <math.h>
#include <float.h>
#include <stdint.h>

// ----------------------------------------------------------------------------
// HierarchicalLoss: total = 0.5*MLM_CE + 0.2*InfoNCE(line) + 0.2*InfoNCE(quat)
//                         + 0.1*Sonnet_selfNCE
// R5: InfoNCE negative loop restructured into explicit load-phase (24 LDG.128
//     batched into a register buffer, one L2 round-trip per iteration) +
//     compute-phase. invnorms staged in shared (kills dependent scalar loads).
// ----------------------------------------------------------------------------

#define INV_TEMP (1.0f / 0.07f)

__device__ float g_partial[4];     // [mlm_sum, line_sum, quat_sum, sonnet_sum]
__device__ int   g_mlm_count;
__device__ int   g_label_stride;   // 1 = int32 labels, 2 = int64 labels (read low word)
__device__ float g_invnorm[1024];  // inverse L2 norms for all small-matrix rows

// ---- streaming logsumexp helpers -------------------------------------------
__device__ __forceinline__ void lse_upd(float& m, float& s, float x) {
    if (x > m) { s = s * __expf(m - x) + 1.0f; m = x; }
    else       { s += __expf(x - m); }
}
__device__ __forceinline__ void lse_combine(float& m, float& s, float m2, float s2) {
    if (s2 <= 0.0f) return;
    if (m2 > m) { s = s * __expf(m - m2) + s2; m = m2; }
    else        { s += s2 * __expf(m2 - m); }
}

// ---- kernel 0: zero accumulators + detect label dtype ----------------------
__global__ void init_detect_kernel(const int* __restrict__ lbl32, int nrows) {
    __shared__ int bad;
    int tid = threadIdx.x;
    if (tid == 0) bad = 0;
    __syncthreads();
    for (int i = tid; i < nrows / 2; i += blockDim.x) {
        int hi = lbl32[2 * i + 1];
        if (hi != 0 && hi != -1) bad = 1;
    }
    __syncthreads();
    if (tid == 0) {
        g_label_stride = bad ? 1 : 2;
        g_partial[0] = 0.0f; g_partial[1] = 0.0f;
        g_partial[2] = 0.0f; g_partial[3] = 0.0f;
        g_mlm_count = 0;
    }
}

// ---- kernel 1: MLM cross-entropy: block per row, early exit, float4 --------
__global__ __launch_bounds__(512) void mlm_kernel(
    const float* __restrict__ logits, const int* __restrict__ lbl32, int V)
{
    int row = blockIdx.x;
    int lbl = lbl32[(size_t)row * g_label_stride];
    if (lbl < 0) return;                     // ignore_index -> zero logits traffic

    const float* __restrict__ x = logits + (size_t)row * V;
    int tid = threadIdx.x;

    float m[8], s[8];
    #pragma unroll
    for (int c = 0; c < 8; c++) { m[c] = -FLT_MAX; s[c] = 0.0f; }

    int head = (((uintptr_t)x) & 15) ? 2 : 0;
    if (tid < head) lse_upd(m[0], s[0], x[tid]);

    const float4* __restrict__ x4 = (const float4*)(x + head);
    int n4 = (V - head) >> 2;
    int tail = (V - head) & 3;

    int i = tid;
    for (; i + 512 < n4; i += 1024) {
        float4 v0 = __ldcs(x4 + i);
        float4 v1 = __ldcs(x4 + i + 512);
        lse_upd(m[0], s[0], v0.x); lse_upd(m[1], s[1], v0.y);
        lse_upd(m[2], s[2], v0.z); lse_upd(m[3], s[3], v0.w);
        lse_upd(m[4], s[4], v1.x); lse_upd(m[5], s[5], v1.y);
        lse_upd(m[6], s[6], v1.z); lse_upd(m[7], s[7], v1.w);
    }
    for (; i < n4; i += 512) {
        float4 v0 = __ldcs(x4 + i);
        lse_upd(m[0], s[0], v0.x); lse_upd(m[1], s[1], v0.y);
        lse_upd(m[2], s[2], v0.z); lse_upd(m[3], s[3], v0.w);
    }
    if (tid < tail) lse_upd(m[4], s[4], x[head + 4 * n4 + tid]);

    #pragma unroll
    for (int st = 4; st; st >>= 1)
        #pragma unroll
        for (int c = 0; c < 8; c++)
            if (c < st) lse_combine(m[c], s[c], m[c + st], s[c + st]);

    float M0 = m[0], S0 = s[0];
    for (int o = 16; o; o >>= 1) {
        float mm = __shfl_xor_sync(0xffffffffu, M0, o);
        float ss = __shfl_xor_sync(0xffffffffu, S0, o);
        lse_combine(M0, S0, mm, ss);
    }
    __shared__ float shm[16], shs[16];
    int w = tid >> 5;
    if ((tid & 31) == 0) { shm[w] = M0; shs[w] = S0; }
    __syncthreads();
    if (tid == 0) {
        float M = shm[0], S = shs[0];
        #pragma unroll
        for (int k = 1; k < 16; k++) lse_combine(M, S, shm[k], shs[k]);
        float xl = __ldg(x + lbl);
        atomicAdd(&g_partial[0], M + logf(S) - xl);
        atomicAdd(&g_mlm_count, 1);
    }
}

// ---- kernel 2: inverse L2 norms for all small-matrix rows ------------------
__global__ __launch_bounds__(256) void norms_kernel(
    const float* p0, const float* p1, const float* p2, const float* p3,
    const float* p4, const float* p5, const float* p6,
    int c0, int c1, int c2, int c3, int c4, int c5, int c6, int D)
{
    const float* ptrs[7] = {p0, p1, p2, p3, p4, p5, p6};
    int cnt[7] = {c0, c1, c2, c3, c4, c5, c6};
    int idx = blockIdx.x, off = 0, seg = 0;
    while (idx >= cnt[seg]) { idx -= cnt[seg]; off += cnt[seg]; seg++; }
    const float4* row = (const float4*)(ptrs[seg] + (size_t)idx * D);
    int D4 = D >> 2;

    float p = 0.f;
    for (int k = threadIdx.x; k < D4; k += 256) {
        float4 v = row[k];
        p += v.x * v.x + v.y * v.y + v.z * v.z + v.w * v.w;
    }
    for (int o = 16; o; o >>= 1) p += __shfl_xor_sync(0xffffffffu, p, o);
    __shared__ float red[8];
    if ((threadIdx.x & 31) == 0) red[threadIdx.x >> 5] = p;
    __syncthreads();
    if (threadIdx.x == 0) {
        float sm = 0.f;
        #pragma unroll
        for (int k = 0; k < 8; k++) sm += red[k];
        g_invnorm[off + idx] = 1.0f / fmaxf(sqrtf(sm), 1e-12f);
    }
}

// ---- kernel 3: fused InfoNCE(line) + InfoNCE(quat) + sonnet loss -----------
__global__ __launch_bounds__(256) void small_losses_kernel(
    const float* __restrict__ LA, const float* __restrict__ LP, const float* __restrict__ LN,
    const float* __restrict__ QA, const float* __restrict__ QP, const float* __restrict__ QN,
    const float* __restrict__ SE,
    int PL, int NL, int PQ, int NQ, int BS, int D,
    int oLA, int oLP, int oLN, int oQA, int oQP, int oQN, int oSE)
{
    __shared__ float4 a_s4[192];     // D=768 -> 192 float4 (normalized anchor)
    __shared__ float invn_s[256];    // inverse norms of negatives (staged)
    __shared__ float red[16];
    __shared__ float sh_pos;

    int b = blockIdx.x;
    int tid = threadIdx.x;
    int D4 = D >> 2;

    if (b >= PL + PQ) {
        // ---- sonnet: one block per row ii, coalesced warp-per-jj dots ----
        int ii = b - (PL + PQ);
        float ia = g_invnorm[oSE + ii];
        const float4* Arow = (const float4*)(SE + (size_t)ii * D);
        for (int k = tid; k < D4; k += 256) {
            float4 v = Arow[k];
            a_s4[k] = make_float4(v.x * ia, v.y * ia, v.z * ia, v.w * ia);
        }
        if (tid < BS) invn_s[tid] = g_invnorm[oSE + tid];
        __syncthreads();
        __shared__ float sh_sim[32];
        int w = tid >> 5, lane = tid & 31;
        for (int jj = w; jj < BS; jj += 8) {
            const float4* nr = (const float4*)(SE + (size_t)jj * D);
            float4 r[6];
            #pragma unroll
            for (int p = 0; p < 6; p++) r[p] = nr[lane + 32 * p];
            float d = 0.f;
            #pragma unroll
            for (int p = 0; p < 6; p++) {
                float4 a = a_s4[lane + 32 * p];
                d += a.x * r[p].x + a.y * r[p].y + a.z * r[p].z + a.w * r[p].w;
            }
            #pragma unroll
            for (int o = 16; o; o >>= 1) d += __shfl_xor_sync(0xffffffffu, d, o);
            if (lane == 0) sh_sim[jj] = d * invn_s[jj] * INV_TEMP;
        }
        __syncthreads();
        if (tid == 0) {
            float M = -FLT_MAX, S = 0.f;
            for (int j = 0; j < BS; j++) lse_upd(M, S, sh_sim[j]);
            atomicAdd(&g_partial[3], M + logf(S) - sh_sim[ii]);
        }
        return;
    }

    // ---- InfoNCE block (one anchor per block) ----
    const float* A; const float* P; const float* Nn;
    const float* inva; const float* invp; const float* invn;
    float* accum; int i, Ncnt;
    if (b < PL) {
        A = LA; P = LP; Nn = LN; i = b; Ncnt = NL;
        inva = g_invnorm + oLA; invp = g_invnorm + oLP; invn = g_invnorm + oLN;
        accum = &g_partial[1];
    } else {
        A = QA; P = QP; Nn = QN; i = b - PL; Ncnt = NQ;
        inva = g_invnorm + oQA; invp = g_invnorm + oQP; invn = g_invnorm + oQN;
        accum = &g_partial[2];
    }

    // stage normalized anchor + negative invnorms in shared
    float ia = inva[i];
    const float4* Arow = (const float4*)(A + (size_t)i * D);
    for (int k = tid; k < D4; k += 256) {
        float4 v = Arow[k];
        a_s4[k] = make_float4(v.x * ia, v.y * ia, v.z * ia, v.w * ia);
    }
    if (tid < Ncnt) invn_s[tid] = invn[tid];
    __syncthreads();

    // positive similarity: full-block float4 dot
    {
        const float4* Prow = (const float4*)(P + (size_t)i * D);
        float part = 0.f;
        for (int k = tid; k < D4; k += 256) {
            float4 a = a_s4[k], p = Prow[k];
            part += a.x * p.x + a.y * p.y + a.z * p.z + a.w * p.w;
        }
        for (int o = 16; o; o >>= 1) part += __shfl_xor_sync(0xffffffffu, part, o);
        if ((tid & 31) == 0) red[tid >> 5] = part;
        __syncthreads();
        if (tid == 0) {
            float ssum = 0.f;
            #pragma unroll
            for (int w = 0; w < 8; w++) ssum += red[w];
            sh_pos = ssum * invp[i] * INV_TEMP;
        }
        __syncthreads();
    }
    float pos = sh_pos;

    // negatives: warp chunk; per iteration, LOAD-PHASE fills 24 float4 regs
    // (24 independent LDG.128 in flight -> one L2 round trip), then COMPUTE.
    int w = tid >> 5, lane = tid & 31;
    int chunk = (Ncnt + 7) >> 3;
    int jbeg = w * chunk;
    int jend = min(jbeg + chunk, Ncnt);

    float m = -FLT_MAX, s = 0.f;
    for (int j = jbeg; j < jend; j += 4) {
        int nv = jend - j;                    // uniform within warp
        // clamped row indices (tail-safe; in practice nv>=4 always)
        int j1 = j + (nv > 1 ? 1 : 0);
        int j2 = j + (nv > 2 ? 2 : 0);
        int j3 = j + (nv > 3 ? 3 : 0);
        const float4* n0 = (const float4*)(Nn + (size_t)j  * D);
        const float4* n1 = (const float4*)(Nn + (size_t)j1 * D);
        const float4* n2 = (const float4*)(Nn + (size_t)j2 * D);
        const float4* n3 = (const float4*)(Nn + (size_t)j3 * D);

        float4 r[24];
        #pragma unroll
        for (int p = 0; p < 6; p++) {
            int kk = lane + 32 * p;
            r[p]      = n0[kk];
            r[6 + p]  = n1[kk];
            r[12 + p] = n2[kk];
            r[18 + p] = n3[kk];
        }

        float d0 = 0.f, d1 = 0.f, d2 = 0.f, d3 = 0.f;
        #pragma unroll
        for (int p = 0; p < 6; p++) {
            float4 a = a_s4[lane + 32 * p];
            d0 += a.x * r[p].x      + a.y * r[p].y      + a.z * r[p].z      + a.w * r[p].w;
            d1 += a.x * r[6+p].x    + a.y * r[6+p].y    + a.z * r[6+p].z    + a.w * r[6+p].w;
            d2 += a.x * r[12+p].x   + a.y * r[12+p].y   + a.z * r[12+p].z   + a.w * r[12+p].w;
            d3 += a.x * r[18+p].x   + a.y * r[18+p].y   + a.z * r[18+p].z   + a.w * r[18+p].w;
        }
        #pragma unroll
        for (int o = 16; o; o >>= 1) {
            d0 += __shfl_xor_sync(0xffffffffu, d0, o);
            d1 += __shfl_xor_sync(0xffffffffu, d1, o);
            d2 += __shfl_xor_sync(0xffffffffu, d2, o);
            d3 += __shfl_xor_sync(0xffffffffu, d3, o);
        }
        lse_upd(m, s, d0 * invn_s[j] * INV_TEMP);
        if (nv > 1) lse_upd(m, s, d1 * invn_s[j + 1] * INV_TEMP);
        if (nv > 2) lse_upd(m, s, d2 * invn_s[j + 2] * INV_TEMP);
        if (nv > 3) lse_upd(m, s, d3 * invn_s[j + 3] * INV_TEMP);
    }
    __syncthreads();          // red[] reuse barrier
    if (lane == 0) { red[w * 2] = m; red[w * 2 + 1] = s; }
    __syncthreads();
    if (tid == 0) {
        float M = pos, S = 1.0f;  // positive term included in logits row
        #pragma unroll
        for (int ww = 0; ww < 8; ww++) lse_combine(M, S, red[2 * ww], red[2 * ww + 1]);
        atomicAdd(accum, M + logf(S) - pos);
    }
}

// ---- kernel 4: final weighted combination ----------------------------------
__global__ void finalize_kernel(float* __restrict__ out,
                                float invPL, float invPQ, float invBS)
{
    if (threadIdx.x == 0 && blockIdx.x == 0) {
        float mlm = g_partial[0] / fmaxf((float)g_mlm_count, 1.0f);
        out[0] = 0.5f * mlm
               + 0.2f * g_partial[1] * invPL
               + 0.2f * g_partial[2] * invPQ
               + 0.1f * g_partial[3] * invBS;
    }
}

// ----------------------------------------------------------------------------
extern "C" void kernel_launch(void* const* d_in, const int* in_sizes, int n_in,
                              void* d_out, int out_size)
{
    const float* mlm_logits = (const float*)d_in[0];
    const int*   labels     = (const int*)d_in[1];
    const float* LA = (const float*)d_in[2];
    const float* LP = (const float*)d_in[3];
    const float* LN = (const float*)d_in[4];
    const float* QA = (const float*)d_in[5];
    const float* QP = (const float*)d_in[6];
    const float* QN = (const float*)d_in[7];
    const float* SE = (const float*)d_in[8];

    const int D  = 768;
    int NR  = in_sizes[1];
    int V   = in_sizes[0] / NR;
    int PL  = in_sizes[2] / D;
    int PLp = in_sizes[3] / D;
    int NL  = in_sizes[4] / D;
    int PQ  = in_sizes[5] / D;
    int PQp = in_sizes[6] / D;
    int NQ  = in_sizes[7] / D;
    int BS  = in_sizes[8] / D;

    int oLA = 0;
    int oLP = oLA + PL;
    int oLN = oLP + PLp;
    int oQA = oLN + NL;
    int oQP = oQA + PQ;
    int oQN = oQP + PQp;
    int oSE = oQN + NQ;
    int totalRows = oSE + BS;

    init_detect_kernel<<<1, 256>>>(labels, NR);
    mlm_kernel<<<NR, 512>>>(mlm_logits, labels, V);
    norms_kernel<<<totalRows, 256>>>(LA, LP, LN, QA, QP, QN, SE,
                                     PL, PLp, NL, PQ, PQp, NQ, BS, D);
    small_losses_kernel<<<PL + PQ + BS, 256>>>(LA, LP, LN, QA, QP, QN, SE,
                                               PL, NL, PQ, NQ, BS, D,
                                               oLA, oLP, oLN, oQA, oQP, oQN, oSE);
    finalize_kernel<<<1, 32>>>((float*)d_out,
                               1.0f / (float)PL, 1.0f / (float)PQ, 1.0f / (float)BS);
}